// round 15
// baseline (speedup 1.0000x reference)
#include <cuda_runtime.h>
#include <cuda_fp16.h>
#include <cstdint>
#include <cstddef>

#define BATCH 4096
#define DIM   1024

// ---------------- scratch (static device memory) ----------------------------
__device__ __half g_wm16[6u * 1024u * 1024u];  // fp16 masked weights
__device__ __half g_x16 [BATCH * DIM];         // fp16 input copy
__device__ __half g_h1s [BATCH * DIM];
__device__ __half g_h2s [BATCH * DIM];
__device__ __half g_h1t [BATCH * DIM];
__device__ __half g_h2t [BATCH * DIM];
__device__ float  g_m   [BATCH * DIM];
__device__ float  g_a   [BATCH * DIM];
__device__ unsigned g_done[2][2][32];          // [layer 0/1 done][branch][M-block]
__device__ unsigned g_fin[32];                  // layer-2 tiles done per strip (0..16)
__device__ unsigned g_prepB;                    // prepB CTAs completed (64 total)

// ---------------- helpers ---------------------------------------------------
__device__ __forceinline__ uint32_t smem_u32(const void* p) {
    uint32_t a;
    asm("{ .reg .u64 t; cvta.to.shared.u64 t, %1; cvt.u32.u64 %0, t; }" : "=r"(a) : "l"(p));
    return a;
}

__device__ __forceinline__ void ldm_x4(uint32_t& r0, uint32_t& r1, uint32_t& r2, uint32_t& r3,
                                       uint32_t addr) {
    asm volatile("ldmatrix.sync.aligned.m8n8.x4.shared.b16 {%0,%1,%2,%3}, [%4];"
                 : "=r"(r0), "=r"(r1), "=r"(r2), "=r"(r3) : "r"(addr));
}

__device__ __forceinline__ void mma_f16(float& d0, float& d1, float& d2, float& d3,
                                        uint32_t a0, uint32_t a1, uint32_t a2, uint32_t a3,
                                        uint32_t b0, uint32_t b1) {
    asm("mma.sync.aligned.m16n8k16.row.col.f32.f16.f16.f32 "
        "{%0,%1,%2,%3},{%4,%5,%6,%7},{%8,%9},{%0,%1,%2,%3};\n"
        : "+f"(d0), "+f"(d1), "+f"(d2), "+f"(d3)
        : "r"(a0), "r"(a1), "r"(a2), "r"(a3), "r"(b0), "r"(b1));
}

#define CP_ASYNC16(dst, src) \
    asm volatile("cp.async.cg.shared.global [%0], [%1], 16;" :: "r"(dst), "l"(src) : "memory")
#define CP_COMMIT() asm volatile("cp.async.commit_group;" ::: "memory")
#define CP_WAIT1()  asm volatile("cp.async.wait_group 1;" ::: "memory")

// ---------------- prepA: x conversion + layer-1 weights (slots 0,3) ----------
// mask_in[o,i] = (o%1023 >= i). Layer-0 GEMM reads only the triangular region
// (c4 < 32*(cb+1)) of slots 0,3. Also zeroes the mega-kernel sync counters.
__global__ void prep_a(const float* __restrict__ sw1, const float* __restrict__ tw1,
                       const float* __restrict__ x,
                       __half* __restrict__ dst, __half* __restrict__ xdst) {
    const size_t WSZ = 1024u * 1024u;
    const int bid = blockIdx.x;
    const int tid = threadIdx.x;
    if (bid == 0) {
        if (tid < 128) (&g_done[0][0][0])[tid] = 0u;
        else if (tid < 160) g_fin[tid - 128] = 0u;
        else if (tid == 160) g_prepB = 0u;
    }
    if (bid >= 1024) {
        // ---- x conversion: 2 float4 per thread (MLP=2) ----
        int i0 = (bid - 1024) * 512 + tid;
        float4 v0 = reinterpret_cast<const float4*>(x)[i0];
        float4 v1 = reinterpret_cast<const float4*>(x)[i0 + 256];
        __half2* d2 = reinterpret_cast<__half2*>(xdst);
        d2[2 * i0]             = __floats2half2_rn(v0.x, v0.y);
        d2[2 * i0 + 1]         = __floats2half2_rn(v0.z, v0.w);
        d2[2 * (i0 + 256)]     = __floats2half2_rn(v1.x, v1.y);
        d2[2 * (i0 + 256) + 1] = __floats2half2_rn(v1.z, v1.w);
        return;
    }
    int i  = bid * 256 + tid;   // over 262144 float4
    int o  = i >> 8;            // output row
    int c4 = i & 255;           // float4 column index
    int cb = o >> 7;
    if (c4 >= 32 * (cb + 1)) return;   // outside triangular region
    const int col0 = c4 * 4;
    const int od = o % 1023;
    float mi[4];
#pragma unroll
    for (int k = 0; k < 4; ++k) mi[k] = (od >= col0 + k) ? 1.f : 0.f;
#define DO_W(wp, mk, slot) { \
        float4 wv = reinterpret_cast<const float4*>(wp)[i]; \
        __half2* d2 = reinterpret_cast<__half2*>(dst + (slot) * WSZ); \
        d2[2 * i]     = __floats2half2_rn(wv.x * mk[0], wv.y * mk[1]); \
        d2[2 * i + 1] = __floats2half2_rn(wv.z * mk[2], wv.w * mk[3]); }
    DO_W(sw1, mi, 0);
    DO_W(tw1, mi, 3);
#undef DO_W
}

// ---------------- single launch: prepB + 3-layer GEMM + strip finale ---------
// Grid = (branch=2, M=32, zc=25); zc slowest. zc==0: prepB CTAs (dispatched
// first, never spin) prepare weight slots 1,2,4,5. zc>=1: zcl=zc-1,
// layer=zcl>>3, cb=7-(zcl&7) (LPT). Layer-1 gates on g_prepB + strip dep;
// layer-2 on strip dep. After a layer-2 tile stores m/a it bumps g_fin[y];
// the 16th (last) tile of each strip computes u=(x-m)*exp(-a) + logdet for
// that strip's 128 rows in the otherwise-dead GEMM tail (no spinning, no
// extra CTAs, no trailing launch).
#define ACT_TANH 0
#define ACT_RELU 1
#define ACT_NONE 2

#define NCH 16
#define STAGES 3
#define ROWB 144
#define STAGE_BYTES (256 * ROWB)
#define B_SMEM_OFF  (128 * ROWB)
#define GEMM_SMEM   (STAGES * STAGE_BYTES)   // 110592

__global__ __launch_bounds__(256, 2)
void gemm_made_kernel(const float* __restrict__ xf, const __half* __restrict__ x16,
                      __half* __restrict__ h1s, __half* __restrict__ h1t,
                      __half* __restrict__ h2s, __half* __restrict__ h2t,
                      __half* __restrict__ wm,
                      const float* __restrict__ sw2, const float* __restrict__ sw3,
                      const float* __restrict__ tw2, const float* __restrict__ tw3,
                      const float* __restrict__ sb1, const float* __restrict__ sb2,
                      const float* __restrict__ sb3, const float* __restrict__ tb1,
                      const float* __restrict__ tb2, const float* __restrict__ tb3,
                      float* __restrict__ mbuf, float* __restrict__ abuf,
                      float* __restrict__ out) {
    extern __shared__ __align__(16) char smc[];
    const uint32_t sbase = smem_u32(smc);
    const size_t WSZ = 1024u * 1024u;

    const int b   = blockIdx.x;            // branch
    const int y   = blockIdx.y;            // M-block
    const int zc  = blockIdx.z;

    const int tid  = threadIdx.x;
    const int warp = tid >> 5;
    const int lane = tid & 31;

    if (zc == 0) {
        // ================= prepB: weight slots 1,2,4,5 (16 rows per CTA) ====
        const int p = b * 32 + y;           // 0..63
#pragma unroll 1
        for (int r = 0; r < 16; ++r) {
            const int o   = p * 16 + r;
            const int cb  = o >> 7;
            const int lim = 32 * (cb + 1);
            const int od  = o % 1023;
            const int total = (cb == 7) ? 256 : (lim + 16);
            for (int t = tid; t < total; t += 256) {
                const int c4 = (t < lim) ? t : (240 + (t - lim));
                const size_t i = ((size_t)o << 8) + c4;
                const int col0 = c4 * 4;
                float mh[4], mo[4];
#pragma unroll
                for (int k = 0; k < 4; ++k) {
                    int cm = (col0 + k) % 1023;
                    mh[k] = (od >= cm)      ? 1.f : 0.f;
                    mo[k] = ((o - 1) >= cm) ? 1.f : 0.f;
                }
#define DO_W(wp, mk, slot) { \
                float4 wv = reinterpret_cast<const float4*>(wp)[i]; \
                __half2* d2 = reinterpret_cast<__half2*>(wm + (slot) * WSZ); \
                d2[2 * i]     = __floats2half2_rn(wv.x * mk[0], wv.y * mk[1]); \
                d2[2 * i + 1] = __floats2half2_rn(wv.z * mk[2], wv.w * mk[3]); }
                DO_W(sw2, mh, 1); DO_W(sw3, mo, 2);
                DO_W(tw2, mh, 4); DO_W(tw3, mo, 5);
#undef DO_W
            }
        }
        __threadfence();
        __syncthreads();
        if (tid == 0) atomicAdd(&g_prepB, 1u);
        return;
    }

    const int zcl   = zc - 1;
    const int layer = zcl >> 3;               // 0,1,2
    const int cb    = 7 - (zcl & 7);          // heavy column blocks first

    // ---- per-(layer,branch) operand selection ----
    const __half* A; const __half* W; const float* bias;
    void* C; int act; bool addlast;
    if (layer == 0) {
        A = x16;                W = wm + (b ? 3 : 0) * WSZ;
        bias = b ? tb1 : sb1;   C = b ? (void*)h1t : (void*)h1s;
        act = b ? ACT_RELU : ACT_TANH;  addlast = false;
    } else if (layer == 1) {
        A = b ? h1t : h1s;      W = wm + (b ? 4 : 1) * WSZ;
        bias = b ? tb2 : sb2;   C = b ? (void*)h2t : (void*)h2s;
        act = b ? ACT_RELU : ACT_TANH;  addlast = true;
    } else {
        A = b ? h2t : h2s;      W = wm + (b ? 5 : 2) * WSZ;
        bias = b ? tb3 : sb3;   C = b ? (void*)abuf : (void*)mbuf;
        act = ACT_NONE;                 addlast = true;
    }

    const int warpM = warp >> 2;
    const int warpN = warp & 3;
    const int qr    = lane >> 2;
    const int qc    = lane & 3;

    const int rowA0 = y * 128;
    const int colB0 = cb * 128;

    // ---- wait for producers ----
    if (layer == 1) {
        if (tid == 0) {
            volatile unsigned* pb = &g_prepB;
            while (*pb < 64u) { __nanosleep(128); }
            volatile unsigned* cnt = &g_done[0][b][y];
            while (*cnt < 8u) { __nanosleep(128); }
            __threadfence();
        }
        __syncthreads();
    } else if (layer == 2) {
        if (tid == 0) {
            volatile unsigned* cnt = &g_done[1][b][y];
            while (*cnt < 8u) { __nanosleep(128); }
            __threadfence();
        }
        __syncthreads();
    }

    // ---- active K-chunk schedule ----
    const int Klim = min(NCH, cb * 2 + 2);
    const int NACT = (addlast && Klim < NCH) ? Klim + 1 : Klim;
#define CHUNK_OF(j) (((j) < Klim) ? (j) : (NCH - 1))

    float acc[4][4][4];
#pragma unroll
    for (int mf = 0; mf < 4; ++mf)
#pragma unroll
        for (int nf = 0; nf < 4; ++nf)
#pragma unroll
            for (int r = 0; r < 4; ++r) acc[mf][nf][r] = 0.f;

    // ---- cp.async slot bases ----
    const int r0 = tid >> 3;
    const int c  = tid & 7;
    const __half* gA = A + (size_t)(rowA0 + r0) * DIM + c * 8;
    const __half* gB = W + (size_t)(colB0 + r0) * DIM + c * 8;
    const uint32_t sA = (uint32_t)(r0 * ROWB + c * 16);
    const uint32_t sB = (uint32_t)(B_SMEM_OFF + r0 * ROWB + c * 16);

#define LOAD_CHUNK(kt, st) do {                                              \
        uint32_t _b = sbase + (uint32_t)(st) * STAGE_BYTES;                  \
        const __half* _ga = gA + (kt) * 64;                                  \
        const __half* _gb = gB + (kt) * 64;                                  \
        _Pragma("unroll")                                                    \
        for (int _i = 0; _i < 4; ++_i) {                                     \
            CP_ASYNC16(_b + sA + _i * (32 * ROWB), _ga + _i * (32 * DIM));   \
            CP_ASYNC16(_b + sB + _i * (32 * ROWB), _gb + _i * (32 * DIM));   \
        }                                                                    \
    } while (0)

    // ---- ldmatrix per-thread base offsets ----
    uint32_t aoff[4], boff[2];
#pragma unroll
    for (int mf = 0; mf < 4; ++mf) {
        int arow = warpM * 64 + mf * 16 + (lane & 15);
        aoff[mf] = (uint32_t)(arow * ROWB + ((lane >> 4) & 1) * 16);
    }
#pragma unroll
    for (int np = 0; np < 2; ++np) {
        int brow = warpN * 32 + np * 16 + (lane & 7) + ((lane >> 4) & 1) * 8;
        boff[np] = (uint32_t)(B_SMEM_OFF + brow * ROWB + ((lane >> 3) & 1) * 16);
    }

    // Prologue: prefetch active chunks 0 and 1 (NACT >= 2 always)
    LOAD_CHUNK(CHUNK_OF(0), 0); CP_COMMIT();
    LOAD_CHUNK(CHUNK_OF(1), 1); CP_COMMIT();

    int st_c = 0;
    for (int j = 0; j < NACT; ++j) {
        CP_WAIT1();
        __syncthreads();

        if (j + 2 < NACT) {
            int st_n = st_c + 2; if (st_n >= STAGES) st_n -= STAGES;
            LOAD_CHUNK(CHUNK_OF(j + 2), st_n);
        }
        CP_COMMIT();

        const uint32_t stb = sbase + (uint32_t)st_c * STAGE_BYTES;
#pragma unroll
        for (int s = 0; s < 4; ++s) {
            uint32_t afr[4][4];
            uint32_t bfr[4][2];
#pragma unroll
            for (int mf = 0; mf < 4; ++mf)
                ldm_x4(afr[mf][0], afr[mf][1], afr[mf][2], afr[mf][3],
                       stb + aoff[mf] + s * 32);
#pragma unroll
            for (int np = 0; np < 2; ++np)
                ldm_x4(bfr[2 * np][0], bfr[2 * np][1],
                       bfr[2 * np + 1][0], bfr[2 * np + 1][1],
                       stb + boff[np] + s * 32);
#pragma unroll
            for (int mf = 0; mf < 4; ++mf)
#pragma unroll
                for (int nf = 0; nf < 4; ++nf)
                    mma_f16(acc[mf][nf][0], acc[mf][nf][1], acc[mf][nf][2], acc[mf][nf][3],
                            afr[mf][0], afr[mf][1], afr[mf][2], afr[mf][3],
                            bfr[nf][0], bfr[nf][1]);
        }
        ++st_c; if (st_c >= STAGES) st_c = 0;
    }
#undef CHUNK_OF
#undef LOAD_CHUNK

    // ---- epilogue: bias + activation ----
#pragma unroll
    for (int mf = 0; mf < 4; ++mf) {
#pragma unroll
        for (int nf = 0; nf < 4; ++nf) {
            int row0 = rowA0 + warpM * 64 + mf * 16 + qr;
            int col0 = colB0 + warpN * 32 + nf * 8 + 2 * qc;
            float b0 = bias[col0];
            float b1 = bias[col0 + 1];
            float v0 = acc[mf][nf][0] + b0;
            float v1 = acc[mf][nf][1] + b1;
            float v2 = acc[mf][nf][2] + b0;
            float v3 = acc[mf][nf][3] + b1;
            if (act == ACT_TANH) {
                v0 = tanhf(v0); v1 = tanhf(v1); v2 = tanhf(v2); v3 = tanhf(v3);
            } else if (act == ACT_RELU) {
                v0 = fmaxf(v0, 0.f); v1 = fmaxf(v1, 0.f);
                v2 = fmaxf(v2, 0.f); v3 = fmaxf(v3, 0.f);
            }
            if (layer < 2) {   // __half intermediate
                __half2* p0 = reinterpret_cast<__half2*>((__half*)C + (size_t)row0 * DIM + col0);
                __half2* p1 = reinterpret_cast<__half2*>((__half*)C + (size_t)(row0 + 8) * DIM + col0);
                *p0 = __floats2half2_rn(v0, v1);
                *p1 = __floats2half2_rn(v2, v3);
            } else {            // float output (m / a)
                *reinterpret_cast<float2*>((float*)C + (size_t)row0 * DIM + col0)       = make_float2(v0, v1);
                *reinterpret_cast<float2*>((float*)C + (size_t)(row0 + 8) * DIM + col0) = make_float2(v2, v3);
            }
        }
    }

    if (layer < 2) {
        // ---- signal completion ----
        __threadfence();
        __syncthreads();
        if (tid == 0) atomicAdd(&g_done[layer][b][y], 1u);
        return;
    }

    // ---- layer-2: bump strip counter; LAST tile (old==15) runs the finale ----
    __threadfence();
    __syncthreads();
    unsigned* s_old = reinterpret_cast<unsigned*>(smc);
    if (tid == 0) *s_old = atomicAdd(&g_fin[y], 1u);
    __syncthreads();
    if (*s_old == 15u) {
        __threadfence();     // see other tiles' m/a stores
        // finale for strip y: rows [y*128, y*128+128); warp w -> 16 rows
#pragma unroll 1
        for (int rr = 0; rr < 16; ++rr) {
            const int row = y * 128 + warp * 16 + rr;
            const float4* ar = reinterpret_cast<const float4*>(abuf + (size_t)row * DIM);
            const float4* mr = reinterpret_cast<const float4*>(mbuf + (size_t)row * DIM);
            const float4* xr = reinterpret_cast<const float4*>(xf   + (size_t)row * DIM);
            float4*       ur = reinterpret_cast<float4*>(out + (size_t)row * DIM);
            float s = 0.f;
#pragma unroll
            for (int k = 0; k < 8; ++k) {
                int idx = lane + 32 * k;
                float4 av = ar[idx];
                float4 mv = mr[idx];
                float4 xv = xr[idx];
                float4 uv;
                uv.x = (xv.x - mv.x) * expf(-av.x);
                uv.y = (xv.y - mv.y) * expf(-av.y);
                uv.z = (xv.z - mv.z) * expf(-av.z);
                uv.w = (xv.w - mv.w) * expf(-av.w);
                ur[idx] = uv;
                s += av.x + av.y + av.z + av.w;
            }
#pragma unroll
            for (int o = 16; o; o >>= 1) s += __shfl_down_sync(0xFFFFFFFFu, s, o);
            if (lane == 0) out[(size_t)BATCH * DIM + row] = -s;
        }
    }
}

// ---------------- launcher ---------------------------------------------------
extern "C" void kernel_launch(void* const* d_in, const int* in_sizes, int n_in,
                              void* d_out, int out_size) {
    (void)in_sizes; (void)n_in; (void)out_size;
    const float* x      = (const float*)d_in[0];
    const float* s_w1   = (const float*)d_in[1];
    const float* s_b1   = (const float*)d_in[2];
    const float* s_w2   = (const float*)d_in[3];
    const float* s_b2   = (const float*)d_in[4];
    const float* s_w3   = (const float*)d_in[5];
    const float* s_b3   = (const float*)d_in[6];
    const float* t_w1   = (const float*)d_in[7];
    const float* t_b1   = (const float*)d_in[8];
    const float* t_w2   = (const float*)d_in[9];
    const float* t_b2   = (const float*)d_in[10];
    const float* t_w3   = (const float*)d_in[11];
    const float* t_b3   = (const float*)d_in[12];
    float* out = (float*)d_out;

    __half *wm, *x16, *h1s, *h2s, *h1t, *h2t;
    float *mbuf, *abuf;
    cudaGetSymbolAddress((void**)&wm,   g_wm16);
    cudaGetSymbolAddress((void**)&x16,  g_x16);
    cudaGetSymbolAddress((void**)&h1s,  g_h1s);
    cudaGetSymbolAddress((void**)&h2s,  g_h2s);
    cudaGetSymbolAddress((void**)&h1t,  g_h1t);
    cudaGetSymbolAddress((void**)&h2t,  g_h2t);
    cudaGetSymbolAddress((void**)&mbuf, g_m);
    cudaGetSymbolAddress((void**)&abuf, g_a);

    cudaFuncSetAttribute((const void*)gemm_made_kernel,
                         cudaFuncAttributeMaxDynamicSharedMemorySize, GEMM_SMEM);

    // prepA: counter reset + x convert (2 float4/thread) + slots 0,3
    prep_a<<<3072, 256>>>(s_w1, t_w1, x, wm, x16);

    // One launch: prepB (zc=0, first) + 3 layers x 2 branches + strip finale.
    dim3 grid(2, BATCH / 128, 25);
    gemm_made_kernel<<<grid, 256, GEMM_SMEM>>>(
        x, x16, h1s, h1t, h2s, h2t, wm,
        s_w2, s_w3, t_w2, t_w3,
        s_b1, s_b2, s_b3, t_b1, t_b2, t_b3, mbuf, abuf, out);
}

// round 16
// speedup vs baseline: 1.4914x; 1.4914x over previous
#include <cuda_runtime.h>
#include <cuda_fp16.h>
#include <cstdint>
#include <cstddef>

#define BATCH 4096
#define DIM   1024

// ---------------- scratch (static device memory) ----------------------------
__device__ __half g_wm16[6u * 1024u * 1024u];  // fp16 masked weights
__device__ __half g_x16 [BATCH * DIM];         // fp16 input copy
__device__ __half g_h1s [BATCH * DIM];
__device__ __half g_h2s [BATCH * DIM];
__device__ __half g_h1t [BATCH * DIM];
__device__ __half g_h2t [BATCH * DIM];
__device__ float  g_m   [BATCH * DIM];
__device__ float  g_a   [BATCH * DIM];
__device__ unsigned g_done[2][2][32];          // [layer 0/1 done][branch][M-block]
__device__ unsigned g_prepB;                    // prepB CTAs completed (64 total)

// ---------------- helpers ---------------------------------------------------
__device__ __forceinline__ uint32_t smem_u32(const void* p) {
    uint32_t a;
    asm("{ .reg .u64 t; cvta.to.shared.u64 t, %1; cvt.u32.u64 %0, t; }" : "=r"(a) : "l"(p));
    return a;
}

__device__ __forceinline__ void ldm_x4(uint32_t& r0, uint32_t& r1, uint32_t& r2, uint32_t& r3,
                                       uint32_t addr) {
    asm volatile("ldmatrix.sync.aligned.m8n8.x4.shared.b16 {%0,%1,%2,%3}, [%4];"
                 : "=r"(r0), "=r"(r1), "=r"(r2), "=r"(r3) : "r"(addr));
}

__device__ __forceinline__ void mma_f16(float& d0, float& d1, float& d2, float& d3,
                                        uint32_t a0, uint32_t a1, uint32_t a2, uint32_t a3,
                                        uint32_t b0, uint32_t b1) {
    asm("mma.sync.aligned.m16n8k16.row.col.f32.f16.f16.f32 "
        "{%0,%1,%2,%3},{%4,%5,%6,%7},{%8,%9},{%0,%1,%2,%3};\n"
        : "+f"(d0), "+f"(d1), "+f"(d2), "+f"(d3)
        : "r"(a0), "r"(a1), "r"(a2), "r"(a3), "r"(b0), "r"(b1));
}

#define CP_ASYNC16(dst, src) \
    asm volatile("cp.async.cg.shared.global [%0], [%1], 16;" :: "r"(dst), "l"(src) : "memory")
#define CP_COMMIT() asm volatile("cp.async.commit_group;" ::: "memory")
#define CP_WAIT1()  asm volatile("cp.async.wait_group 1;" ::: "memory")

// ---------------- prepA: x conversion + layer-1 weights (slots 0,3) ----------
// mask_in[o,i] = (o%1023 >= i). Layer-0 GEMM reads only the triangular region
// (c4 < 32*(cb+1)) of slots 0,3. Also zeroes the mega-kernel sync counters.
__global__ void prep_a(const float* __restrict__ sw1, const float* __restrict__ tw1,
                       const float* __restrict__ x,
                       __half* __restrict__ dst, __half* __restrict__ xdst) {
    const size_t WSZ = 1024u * 1024u;
    const int bid = blockIdx.x;
    const int tid = threadIdx.x;
    if (bid == 0) {
        if (tid < 128) (&g_done[0][0][0])[tid] = 0u;
        else if (tid == 128) g_prepB = 0u;
    }
    if (bid >= 1024) {
        // ---- x conversion: 2 float4 per thread (MLP=2) ----
        int i0 = (bid - 1024) * 512 + tid;
        float4 v0 = reinterpret_cast<const float4*>(x)[i0];
        float4 v1 = reinterpret_cast<const float4*>(x)[i0 + 256];
        __half2* d2 = reinterpret_cast<__half2*>(xdst);
        d2[2 * i0]             = __floats2half2_rn(v0.x, v0.y);
        d2[2 * i0 + 1]         = __floats2half2_rn(v0.z, v0.w);
        d2[2 * (i0 + 256)]     = __floats2half2_rn(v1.x, v1.y);
        d2[2 * (i0 + 256) + 1] = __floats2half2_rn(v1.z, v1.w);
        return;
    }
    int i  = bid * 256 + tid;   // over 262144 float4
    int o  = i >> 8;            // output row
    int c4 = i & 255;           // float4 column index
    int cb = o >> 7;
    if (c4 >= 32 * (cb + 1)) return;   // outside triangular region
    const int col0 = c4 * 4;
    const int od = o % 1023;
    float mi[4];
#pragma unroll
    for (int k = 0; k < 4; ++k) mi[k] = (od >= col0 + k) ? 1.f : 0.f;
#define DO_W(wp, mk, slot) { \
        float4 wv = reinterpret_cast<const float4*>(wp)[i]; \
        __half2* d2 = reinterpret_cast<__half2*>(dst + (slot) * WSZ); \
        d2[2 * i]     = __floats2half2_rn(wv.x * mk[0], wv.y * mk[1]); \
        d2[2 * i + 1] = __floats2half2_rn(wv.z * mk[2], wv.w * mk[3]); }
    DO_W(sw1, mi, 0);
    DO_W(tw1, mi, 3);
#undef DO_W
}

// ---------------- single-launch: prepB + 3-layer dual-branch GEMM ------------
// Grid = (branch=2, M=32, zc=25); zc slowest. zc==0: prepB CTAs (64, dispatched
// FIRST, never spin) prepare weight slots 1,2,4,5 (mask_hid / mask_out,
// triangular + wrap chunk). zc>=1: zcl=zc-1, layer=zcl>>3, cb=7-(zcl&7) (LPT).
// Layer-1 tiles gate on g_prepB==64 + strip dep; layer-2 on strip dep only
// (prepB guaranteed transitively). fp16 in, fp32 acc; CTA tile 128x128, BK=64,
// 256 threads, warp tile 64x32, 3-stage cp.async (110 KB smem -> 2 CTAs/SM).
#define ACT_TANH 0
#define ACT_RELU 1
#define ACT_NONE 2

#define NCH 16
#define STAGES 3
#define ROWB 144
#define STAGE_BYTES (256 * ROWB)
#define B_SMEM_OFF  (128 * ROWB)
#define GEMM_SMEM   (STAGES * STAGE_BYTES)   // 110592

__global__ __launch_bounds__(256, 2)
void gemm_made_kernel(const __half* __restrict__ x16,
                      __half* __restrict__ h1s, __half* __restrict__ h1t,
                      __half* __restrict__ h2s, __half* __restrict__ h2t,
                      __half* __restrict__ wm,
                      const float* __restrict__ sw2, const float* __restrict__ sw3,
                      const float* __restrict__ tw2, const float* __restrict__ tw3,
                      const float* __restrict__ sb1, const float* __restrict__ sb2,
                      const float* __restrict__ sb3, const float* __restrict__ tb1,
                      const float* __restrict__ tb2, const float* __restrict__ tb3,
                      float* __restrict__ mbuf, float* __restrict__ abuf) {
    extern __shared__ __align__(16) char smc[];
    const uint32_t sbase = smem_u32(smc);
    const size_t WSZ = 1024u * 1024u;

    const int b   = blockIdx.x;            // branch
    const int y   = blockIdx.y;            // M-block
    const int zc  = blockIdx.z;

    const int tid  = threadIdx.x;
    const int warp = tid >> 5;
    const int lane = tid & 31;

    if (zc == 0) {
        // ================= prepB: weight slots 1,2,4,5 (16 rows per CTA) ====
        const int p = b * 32 + y;           // 0..63
#pragma unroll 1
        for (int r = 0; r < 16; ++r) {
            const int o   = p * 16 + r;
            const int cb  = o >> 7;
            const int lim = 32 * (cb + 1);
            const int od  = o % 1023;
            const int total = (cb == 7) ? 256 : (lim + 16);
            for (int t = tid; t < total; t += 256) {
                const int c4 = (t < lim) ? t : (240 + (t - lim));
                const size_t i = ((size_t)o << 8) + c4;
                const int col0 = c4 * 4;
                float mh[4], mo[4];
#pragma unroll
                for (int k = 0; k < 4; ++k) {
                    int cm = (col0 + k) % 1023;
                    mh[k] = (od >= cm)      ? 1.f : 0.f;
                    mo[k] = ((o - 1) >= cm) ? 1.f : 0.f;
                }
#define DO_W(wp, mk, slot) { \
                float4 wv = reinterpret_cast<const float4*>(wp)[i]; \
                __half2* d2 = reinterpret_cast<__half2*>(wm + (slot) * WSZ); \
                d2[2 * i]     = __floats2half2_rn(wv.x * mk[0], wv.y * mk[1]); \
                d2[2 * i + 1] = __floats2half2_rn(wv.z * mk[2], wv.w * mk[3]); }
                DO_W(sw2, mh, 1); DO_W(sw3, mo, 2);
                DO_W(tw2, mh, 4); DO_W(tw3, mo, 5);
#undef DO_W
            }
        }
        __threadfence();
        __syncthreads();
        if (tid == 0) atomicAdd(&g_prepB, 1u);
        return;
    }

    const int zcl   = zc - 1;
    const int layer = zcl >> 3;               // 0,1,2
    const int cb    = 7 - (zcl & 7);          // heavy column blocks first

    // ---- per-(layer,branch) operand selection ----
    const __half* A; const __half* W; const float* bias;
    void* C; int act; bool addlast;
    if (layer == 0) {
        A = x16;                W = wm + (b ? 3 : 0) * WSZ;
        bias = b ? tb1 : sb1;   C = b ? (void*)h1t : (void*)h1s;
        act = b ? ACT_RELU : ACT_TANH;  addlast = false;
    } else if (layer == 1) {
        A = b ? h1t : h1s;      W = wm + (b ? 4 : 1) * WSZ;
        bias = b ? tb2 : sb2;   C = b ? (void*)h2t : (void*)h2s;
        act = b ? ACT_RELU : ACT_TANH;  addlast = true;
    } else {
        A = b ? h2t : h2s;      W = wm + (b ? 5 : 2) * WSZ;
        bias = b ? tb3 : sb3;   C = b ? (void*)abuf : (void*)mbuf;
        act = ACT_NONE;                 addlast = true;
    }

    const int warpM = warp >> 2;
    const int warpN = warp & 3;
    const int qr    = lane >> 2;
    const int qc    = lane & 3;

    const int rowA0 = y * 128;
    const int colB0 = cb * 128;

    // ---- wait for producers ----
    if (layer == 1) {
        if (tid == 0) {
            volatile unsigned* pb = &g_prepB;
            while (*pb < 64u) { __nanosleep(128); }
            volatile unsigned* cnt = &g_done[0][b][y];
            while (*cnt < 8u) { __nanosleep(128); }
            __threadfence();
        }
        __syncthreads();
    } else if (layer == 2) {
        if (tid == 0) {
            volatile unsigned* cnt = &g_done[1][b][y];
            while (*cnt < 8u) { __nanosleep(128); }
            __threadfence();
        }
        __syncthreads();
    }

    // ---- active K-chunk schedule ----
    const int Klim = min(NCH, cb * 2 + 2);
    const int NACT = (addlast && Klim < NCH) ? Klim + 1 : Klim;
#define CHUNK_OF(j) (((j) < Klim) ? (j) : (NCH - 1))

    float acc[4][4][4];
#pragma unroll
    for (int mf = 0; mf < 4; ++mf)
#pragma unroll
        for (int nf = 0; nf < 4; ++nf)
#pragma unroll
            for (int r = 0; r < 4; ++r) acc[mf][nf][r] = 0.f;

    // ---- cp.async slot bases ----
    const int r0 = tid >> 3;
    const int c  = tid & 7;
    const __half* gA = A + (size_t)(rowA0 + r0) * DIM + c * 8;
    const __half* gB = W + (size_t)(colB0 + r0) * DIM + c * 8;
    const uint32_t sA = (uint32_t)(r0 * ROWB + c * 16);
    const uint32_t sB = (uint32_t)(B_SMEM_OFF + r0 * ROWB + c * 16);

#define LOAD_CHUNK(kt, st) do {                                              \
        uint32_t _b = sbase + (uint32_t)(st) * STAGE_BYTES;                  \
        const __half* _ga = gA + (kt) * 64;                                  \
        const __half* _gb = gB + (kt) * 64;                                  \
        _Pragma("unroll")                                                    \
        for (int _i = 0; _i < 4; ++_i) {                                     \
            CP_ASYNC16(_b + sA + _i * (32 * ROWB), _ga + _i * (32 * DIM));   \
            CP_ASYNC16(_b + sB + _i * (32 * ROWB), _gb + _i * (32 * DIM));   \
        }                                                                    \
    } while (0)

    // ---- ldmatrix per-thread base offsets ----
    uint32_t aoff[4], boff[2];
#pragma unroll
    for (int mf = 0; mf < 4; ++mf) {
        int arow = warpM * 64 + mf * 16 + (lane & 15);
        aoff[mf] = (uint32_t)(arow * ROWB + ((lane >> 4) & 1) * 16);
    }
#pragma unroll
    for (int np = 0; np < 2; ++np) {
        int brow = warpN * 32 + np * 16 + (lane & 7) + ((lane >> 4) & 1) * 8;
        boff[np] = (uint32_t)(B_SMEM_OFF + brow * ROWB + ((lane >> 3) & 1) * 16);
    }

    // Prologue: prefetch active chunks 0 and 1 (NACT >= 2 always)
    LOAD_CHUNK(CHUNK_OF(0), 0); CP_COMMIT();
    LOAD_CHUNK(CHUNK_OF(1), 1); CP_COMMIT();

    int st_c = 0;
    for (int j = 0; j < NACT; ++j) {
        CP_WAIT1();
        __syncthreads();

        if (j + 2 < NACT) {
            int st_n = st_c + 2; if (st_n >= STAGES) st_n -= STAGES;
            LOAD_CHUNK(CHUNK_OF(j + 2), st_n);
        }
        CP_COMMIT();

        const uint32_t stb = sbase + (uint32_t)st_c * STAGE_BYTES;
#pragma unroll
        for (int s = 0; s < 4; ++s) {
            uint32_t afr[4][4];
            uint32_t bfr[4][2];
#pragma unroll
            for (int mf = 0; mf < 4; ++mf)
                ldm_x4(afr[mf][0], afr[mf][1], afr[mf][2], afr[mf][3],
                       stb + aoff[mf] + s * 32);
#pragma unroll
            for (int np = 0; np < 2; ++np)
                ldm_x4(bfr[2 * np][0], bfr[2 * np][1],
                       bfr[2 * np + 1][0], bfr[2 * np + 1][1],
                       stb + boff[np] + s * 32);
#pragma unroll
            for (int mf = 0; mf < 4; ++mf)
#pragma unroll
                for (int nf = 0; nf < 4; ++nf)
                    mma_f16(acc[mf][nf][0], acc[mf][nf][1], acc[mf][nf][2], acc[mf][nf][3],
                            afr[mf][0], afr[mf][1], afr[mf][2], afr[mf][3],
                            bfr[nf][0], bfr[nf][1]);
        }
        ++st_c; if (st_c >= STAGES) st_c = 0;
    }
#undef CHUNK_OF
#undef LOAD_CHUNK

    // ---- epilogue: bias + activation ----
#pragma unroll
    for (int mf = 0; mf < 4; ++mf) {
#pragma unroll
        for (int nf = 0; nf < 4; ++nf) {
            int row0 = rowA0 + warpM * 64 + mf * 16 + qr;
            int col0 = colB0 + warpN * 32 + nf * 8 + 2 * qc;
            float b0 = bias[col0];
            float b1 = bias[col0 + 1];
            float v0 = acc[mf][nf][0] + b0;
            float v1 = acc[mf][nf][1] + b1;
            float v2 = acc[mf][nf][2] + b0;
            float v3 = acc[mf][nf][3] + b1;
            if (act == ACT_TANH) {
                v0 = tanhf(v0); v1 = tanhf(v1); v2 = tanhf(v2); v3 = tanhf(v3);
            } else if (act == ACT_RELU) {
                v0 = fmaxf(v0, 0.f); v1 = fmaxf(v1, 0.f);
                v2 = fmaxf(v2, 0.f); v3 = fmaxf(v3, 0.f);
            }
            if (layer < 2) {   // __half intermediate
                __half2* p0 = reinterpret_cast<__half2*>((__half*)C + (size_t)row0 * DIM + col0);
                __half2* p1 = reinterpret_cast<__half2*>((__half*)C + (size_t)(row0 + 8) * DIM + col0);
                *p0 = __floats2half2_rn(v0, v1);
                *p1 = __floats2half2_rn(v2, v3);
            } else {            // float output (m / a)
                *reinterpret_cast<float2*>((float*)C + (size_t)row0 * DIM + col0)       = make_float2(v0, v1);
                *reinterpret_cast<float2*>((float*)C + (size_t)(row0 + 8) * DIM + col0) = make_float2(v2, v3);
            }
        }
    }

    // ---- signal completion (layers 0,1 feed a consumer) ----
    if (layer < 2) {
        __threadfence();
        __syncthreads();
        if (tid == 0) atomicAdd(&g_done[layer][b][y], 1u);
    }
}

// ---------------- final elementwise + logdet (2 rows/block, MLP=2) -----------
__global__ void final_kernel(const float* __restrict__ x, const float* __restrict__ m,
                             const float* __restrict__ a, float* __restrict__ out) {
    const int t   = threadIdx.x;
    const int row = blockIdx.x * 2 + (t >> 7);   // 2 rows per block
    const int j   = t & 127;                      // float4 lane within row
    const size_t rb4 = (size_t)row * (DIM / 4);
    const float4* ar = reinterpret_cast<const float4*>(a);
    const float4* mr = reinterpret_cast<const float4*>(m);
    const float4* xr = reinterpret_cast<const float4*>(x);
    float4* ur = reinterpret_cast<float4*>(out);

    float4 a0 = ar[rb4 + j];
    float4 a1 = ar[rb4 + j + 128];
    float4 m0 = mr[rb4 + j];
    float4 m1 = mr[rb4 + j + 128];
    float4 x0 = xr[rb4 + j];
    float4 x1 = xr[rb4 + j + 128];
    float4 u0, u1;
    u0.x = (x0.x - m0.x) * expf(-a0.x);
    u0.y = (x0.y - m0.y) * expf(-a0.y);
    u0.z = (x0.z - m0.z) * expf(-a0.z);
    u0.w = (x0.w - m0.w) * expf(-a0.w);
    u1.x = (x1.x - m1.x) * expf(-a1.x);
    u1.y = (x1.y - m1.y) * expf(-a1.y);
    u1.z = (x1.z - m1.z) * expf(-a1.z);
    u1.w = (x1.w - m1.w) * expf(-a1.w);
    ur[rb4 + j]       = u0;
    ur[rb4 + j + 128] = u1;

    float s = a0.x + a0.y + a0.z + a0.w + a1.x + a1.y + a1.z + a1.w;
#pragma unroll
    for (int o = 16; o; o >>= 1) s += __shfl_down_sync(0xFFFFFFFFu, s, o);
    __shared__ float ws[8];
    if ((t & 31) == 0) ws[t >> 5] = s;
    __syncthreads();
    if ((t & 127) == 0) {
        const int wbase = (t >> 7) * 4;
        float v = ws[wbase] + ws[wbase + 1] + ws[wbase + 2] + ws[wbase + 3];
        out[(size_t)BATCH * DIM + row] = -v;
    }
}

// ---------------- launcher ---------------------------------------------------
extern "C" void kernel_launch(void* const* d_in, const int* in_sizes, int n_in,
                              void* d_out, int out_size) {
    (void)in_sizes; (void)n_in; (void)out_size;
    const float* x      = (const float*)d_in[0];
    const float* s_w1   = (const float*)d_in[1];
    const float* s_b1   = (const float*)d_in[2];
    const float* s_w2   = (const float*)d_in[3];
    const float* s_b2   = (const float*)d_in[4];
    const float* s_w3   = (const float*)d_in[5];
    const float* s_b3   = (const float*)d_in[6];
    const float* t_w1   = (const float*)d_in[7];
    const float* t_b1   = (const float*)d_in[8];
    const float* t_w2   = (const float*)d_in[9];
    const float* t_b2   = (const float*)d_in[10];
    const float* t_w3   = (const float*)d_in[11];
    const float* t_b3   = (const float*)d_in[12];
    float* out = (float*)d_out;

    __half *wm, *x16, *h1s, *h2s, *h1t, *h2t;
    float *mbuf, *abuf;
    cudaGetSymbolAddress((void**)&wm,   g_wm16);
    cudaGetSymbolAddress((void**)&x16,  g_x16);
    cudaGetSymbolAddress((void**)&h1s,  g_h1s);
    cudaGetSymbolAddress((void**)&h2s,  g_h2s);
    cudaGetSymbolAddress((void**)&h1t,  g_h1t);
    cudaGetSymbolAddress((void**)&h2t,  g_h2t);
    cudaGetSymbolAddress((void**)&mbuf, g_m);
    cudaGetSymbolAddress((void**)&abuf, g_a);

    cudaFuncSetAttribute((const void*)gemm_made_kernel,
                         cudaFuncAttributeMaxDynamicSharedMemorySize, GEMM_SMEM);

    // prepA: counter reset + x convert (MLP=2) + layer-1 weights (slots 0,3)
    prep_a<<<3072, 256>>>(s_w1, t_w1, x, wm, x16);

    // One launch: prepB (zc=0, dispatched first) + 3 layers x 2 branches.
    dim3 grid(2, BATCH / 128, 25);
    gemm_made_kernel<<<grid, 256, GEMM_SMEM>>>(
        x16, h1s, h1t, h2s, h2t, wm,
        s_w2, s_w3, t_w2, t_w3,
        s_b1, s_b2, s_b3, t_b1, t_b2, t_b3, mbuf, abuf);

    final_kernel<<<BATCH / 2, 256>>>(x, mbuf, abuf, out);
}

// round 17
// speedup vs baseline: 1.5040x; 1.0084x over previous
#include <cuda_runtime.h>
#include <cuda_fp16.h>
#include <cstdint>
#include <cstddef>

#define BATCH 4096
#define DIM   1024

// ---------------- scratch (static device memory) ----------------------------
__device__ __half g_wm16[6u * 1024u * 1024u];  // fp16 masked weights
__device__ __half g_x16 [BATCH * DIM];         // fp16 input copy
__device__ __half g_h1s [BATCH * DIM];
__device__ __half g_h2s [BATCH * DIM];
__device__ __half g_h1t [BATCH * DIM];
__device__ __half g_h2t [BATCH * DIM];
__device__ float  g_m   [BATCH * DIM];
__device__ float  g_a   [BATCH * DIM];
__device__ unsigned g_done[2][2][32];          // [layer 0/1 done][branch][M-block]
__device__ unsigned g_prepB;                    // prepB CTAs completed (64 total)

// ---------------- helpers ---------------------------------------------------
__device__ __forceinline__ uint32_t smem_u32(const void* p) {
    uint32_t a;
    asm("{ .reg .u64 t; cvta.to.shared.u64 t, %1; cvt.u32.u64 %0, t; }" : "=r"(a) : "l"(p));
    return a;
}

__device__ __forceinline__ void ldm_x4(uint32_t& r0, uint32_t& r1, uint32_t& r2, uint32_t& r3,
                                       uint32_t addr) {
    asm volatile("ldmatrix.sync.aligned.m8n8.x4.shared.b16 {%0,%1,%2,%3}, [%4];"
                 : "=r"(r0), "=r"(r1), "=r"(r2), "=r"(r3) : "r"(addr));
}

__device__ __forceinline__ void mma_f16(float& d0, float& d1, float& d2, float& d3,
                                        uint32_t a0, uint32_t a1, uint32_t a2, uint32_t a3,
                                        uint32_t b0, uint32_t b1) {
    asm("mma.sync.aligned.m16n8k16.row.col.f32.f16.f16.f32 "
        "{%0,%1,%2,%3},{%4,%5,%6,%7},{%8,%9},{%0,%1,%2,%3};\n"
        : "+f"(d0), "+f"(d1), "+f"(d2), "+f"(d3)
        : "r"(a0), "r"(a1), "r"(a2), "r"(a3), "r"(b0), "r"(b1));
}

#define CP_ASYNC16(dst, src) \
    asm volatile("cp.async.cg.shared.global [%0], [%1], 16;" :: "r"(dst), "l"(src) : "memory")
#define CP_COMMIT() asm volatile("cp.async.commit_group;" ::: "memory")
#define CP_WAIT1()  asm volatile("cp.async.wait_group 1;" ::: "memory")

// ---------------- prepA: x conversion + layer-1 weights (slots 0,3) ----------
// mask_in[o,i] = (o%1023 >= i). Layer-0 GEMM reads only the triangular region
// (c4 < 32*(cb+1)) of slots 0,3. Also zeroes the mega-kernel sync counters.
__global__ void prep_a(const float* __restrict__ sw1, const float* __restrict__ tw1,
                       const float* __restrict__ x,
                       __half* __restrict__ dst, __half* __restrict__ xdst) {
    const size_t WSZ = 1024u * 1024u;
    const int bid = blockIdx.x;
    const int tid = threadIdx.x;
    if (bid == 0) {
        if (tid < 128) (&g_done[0][0][0])[tid] = 0u;
        else if (tid == 128) g_prepB = 0u;
    }
    if (bid >= 1024) {
        // ---- x conversion: 2 float4 per thread (MLP=2) ----
        int i0 = (bid - 1024) * 512 + tid;
        float4 v0 = reinterpret_cast<const float4*>(x)[i0];
        float4 v1 = reinterpret_cast<const float4*>(x)[i0 + 256];
        __half2* d2 = reinterpret_cast<__half2*>(xdst);
        d2[2 * i0]             = __floats2half2_rn(v0.x, v0.y);
        d2[2 * i0 + 1]         = __floats2half2_rn(v0.z, v0.w);
        d2[2 * (i0 + 256)]     = __floats2half2_rn(v1.x, v1.y);
        d2[2 * (i0 + 256) + 1] = __floats2half2_rn(v1.z, v1.w);
        return;
    }
    int i  = bid * 256 + tid;   // over 262144 float4
    int o  = i >> 8;            // output row
    int c4 = i & 255;           // float4 column index
    int cb = o >> 7;
    if (c4 >= 32 * (cb + 1)) return;   // outside triangular region
    const int col0 = c4 * 4;
    const int od = o % 1023;
    float mi[4];
#pragma unroll
    for (int k = 0; k < 4; ++k) mi[k] = (od >= col0 + k) ? 1.f : 0.f;
#define DO_W(wp, mk, slot) { \
        float4 wv = reinterpret_cast<const float4*>(wp)[i]; \
        __half2* d2 = reinterpret_cast<__half2*>(dst + (slot) * WSZ); \
        d2[2 * i]     = __floats2half2_rn(wv.x * mk[0], wv.y * mk[1]); \
        d2[2 * i + 1] = __floats2half2_rn(wv.z * mk[2], wv.w * mk[3]); }
    DO_W(sw1, mi, 0);
    DO_W(tw1, mi, 3);
#undef DO_W
}

// ---------------- single-launch: prepB + 3-layer dual-branch GEMM ------------
// Grid = (branch=2, M=32, zc=25); zc slowest. zc==0: prepB CTAs (64, dispatched
// FIRST, never spin) prepare weight slots 1,2,4,5. zc>=1: zcl=zc-1,
// layer=zcl>>3, cb=7-(zcl&7) (LPT). Layer-1 gates on g_prepB + strip dep;
// layer-2 on strip dep. WRAP-CHUNK FOLDING: for %1023-masked layers, tiles
// with cb<7 skip the wrap chunk entirely — its only nonzero column (i=1023)
// is applied as a rank-1 epilogue FMA (bit-identical: fp16 products are exact
// in fp32, so fmaf(a,w,acc) == MMA's acc + product with one rounding).
#define ACT_TANH 0
#define ACT_RELU 1
#define ACT_NONE 2

#define NCH 16
#define STAGES 3
#define ROWB 144
#define STAGE_BYTES (256 * ROWB)
#define B_SMEM_OFF  (128 * ROWB)
#define GEMM_SMEM   (STAGES * STAGE_BYTES)   // 110592

__global__ __launch_bounds__(256, 2)
void gemm_made_kernel(const __half* __restrict__ x16,
                      __half* __restrict__ h1s, __half* __restrict__ h1t,
                      __half* __restrict__ h2s, __half* __restrict__ h2t,
                      __half* __restrict__ wm,
                      const float* __restrict__ sw2, const float* __restrict__ sw3,
                      const float* __restrict__ tw2, const float* __restrict__ tw3,
                      const float* __restrict__ sb1, const float* __restrict__ sb2,
                      const float* __restrict__ sb3, const float* __restrict__ tb1,
                      const float* __restrict__ tb2, const float* __restrict__ tb3,
                      float* __restrict__ mbuf, float* __restrict__ abuf) {
    extern __shared__ __align__(16) char smc[];
    const uint32_t sbase = smem_u32(smc);
    const size_t WSZ = 1024u * 1024u;

    const int b   = blockIdx.x;            // branch
    const int y   = blockIdx.y;            // M-block
    const int zc  = blockIdx.z;

    const int tid  = threadIdx.x;
    const int warp = tid >> 5;
    const int lane = tid & 31;

    if (zc == 0) {
        // ================= prepB: weight slots 1,2,4,5 (16 rows per CTA) ====
        const int p = b * 32 + y;           // 0..63
#pragma unroll 1
        for (int r = 0; r < 16; ++r) {
            const int o   = p * 16 + r;
            const int cb  = o >> 7;
            const int lim = 32 * (cb + 1);
            const int od  = o % 1023;
            const int total = (cb == 7) ? 256 : (lim + 16);
            for (int t = tid; t < total; t += 256) {
                const int c4 = (t < lim) ? t : (240 + (t - lim));
                const size_t i = ((size_t)o << 8) + c4;
                const int col0 = c4 * 4;
                float mh[4], mo[4];
#pragma unroll
                for (int k = 0; k < 4; ++k) {
                    int cm = (col0 + k) % 1023;
                    mh[k] = (od >= cm)      ? 1.f : 0.f;
                    mo[k] = ((o - 1) >= cm) ? 1.f : 0.f;
                }
#define DO_W(wp, mk, slot) { \
                float4 wv = reinterpret_cast<const float4*>(wp)[i]; \
                __half2* d2 = reinterpret_cast<__half2*>(wm + (slot) * WSZ); \
                d2[2 * i]     = __floats2half2_rn(wv.x * mk[0], wv.y * mk[1]); \
                d2[2 * i + 1] = __floats2half2_rn(wv.z * mk[2], wv.w * mk[3]); }
                DO_W(sw2, mh, 1); DO_W(sw3, mo, 2);
                DO_W(tw2, mh, 4); DO_W(tw3, mo, 5);
#undef DO_W
            }
        }
        __threadfence();
        __syncthreads();
        if (tid == 0) atomicAdd(&g_prepB, 1u);
        return;
    }

    const int zcl   = zc - 1;
    const int layer = zcl >> 3;               // 0,1,2
    const int cb    = 7 - (zcl & 7);          // heavy column blocks first

    // ---- per-(layer,branch) operand selection ----
    const __half* A; const __half* W; const float* bias;
    void* C; int act; bool addlast;
    if (layer == 0) {
        A = x16;                W = wm + (b ? 3 : 0) * WSZ;
        bias = b ? tb1 : sb1;   C = b ? (void*)h1t : (void*)h1s;
        act = b ? ACT_RELU : ACT_TANH;  addlast = false;
    } else if (layer == 1) {
        A = b ? h1t : h1s;      W = wm + (b ? 4 : 1) * WSZ;
        bias = b ? tb2 : sb2;   C = b ? (void*)h2t : (void*)h2s;
        act = b ? ACT_RELU : ACT_TANH;  addlast = true;
    } else {
        A = b ? h2t : h2s;      W = wm + (b ? 5 : 2) * WSZ;
        bias = b ? tb3 : sb3;   C = b ? (void*)abuf : (void*)mbuf;
        act = ACT_NONE;                 addlast = true;
    }

    const int warpM = warp >> 2;
    const int warpN = warp & 3;
    const int qr    = lane >> 2;
    const int qc    = lane & 3;

    const int rowA0 = y * 128;
    const int colB0 = cb * 128;

    // ---- wait for producers ----
    if (layer == 1) {
        if (tid == 0) {
            volatile unsigned* pb = &g_prepB;
            while (*pb < 64u) { __nanosleep(128); }
            volatile unsigned* cnt = &g_done[0][b][y];
            while (*cnt < 8u) { __nanosleep(128); }
            __threadfence();
        }
        __syncthreads();
    } else if (layer == 2) {
        if (tid == 0) {
            volatile unsigned* cnt = &g_done[1][b][y];
            while (*cnt < 8u) { __nanosleep(128); }
            __threadfence();
        }
        __syncthreads();
    }

    // ---- active K-chunk schedule (wrap chunk folded into rank-1 epilogue) ----
    const int  Klim  = min(NCH, cb * 2 + 2);
    const int  NACT  = Klim;
    const bool rank1 = addlast && (Klim < NCH);

    float acc[4][4][4];
#pragma unroll
    for (int mf = 0; mf < 4; ++mf)
#pragma unroll
        for (int nf = 0; nf < 4; ++nf)
#pragma unroll
            for (int r = 0; r < 4; ++r) acc[mf][nf][r] = 0.f;

    // ---- cp.async slot bases ----
    const int r0 = tid >> 3;
    const int c  = tid & 7;
    const __half* gA = A + (size_t)(rowA0 + r0) * DIM + c * 8;
    const __half* gB = W + (size_t)(colB0 + r0) * DIM + c * 8;
    const uint32_t sA = (uint32_t)(r0 * ROWB + c * 16);
    const uint32_t sB = (uint32_t)(B_SMEM_OFF + r0 * ROWB + c * 16);

#define LOAD_CHUNK(kt, st) do {                                              \
        uint32_t _b = sbase + (uint32_t)(st) * STAGE_BYTES;                  \
        const __half* _ga = gA + (kt) * 64;                                  \
        const __half* _gb = gB + (kt) * 64;                                  \
        _Pragma("unroll")                                                    \
        for (int _i = 0; _i < 4; ++_i) {                                     \
            CP_ASYNC16(_b + sA + _i * (32 * ROWB), _ga + _i * (32 * DIM));   \
            CP_ASYNC16(_b + sB + _i * (32 * ROWB), _gb + _i * (32 * DIM));   \
        }                                                                    \
    } while (0)

    // ---- ldmatrix per-thread base offsets ----
    uint32_t aoff[4], boff[2];
#pragma unroll
    for (int mf = 0; mf < 4; ++mf) {
        int arow = warpM * 64 + mf * 16 + (lane & 15);
        aoff[mf] = (uint32_t)(arow * ROWB + ((lane >> 4) & 1) * 16);
    }
#pragma unroll
    for (int np = 0; np < 2; ++np) {
        int brow = warpN * 32 + np * 16 + (lane & 7) + ((lane >> 4) & 1) * 8;
        boff[np] = (uint32_t)(B_SMEM_OFF + brow * ROWB + ((lane >> 3) & 1) * 16);
    }

    // Prologue: prefetch chunks 0 and 1 (NACT >= 2 always)
    LOAD_CHUNK(0, 0); CP_COMMIT();
    LOAD_CHUNK(1, 1); CP_COMMIT();

    int st_c = 0;
    for (int j = 0; j < NACT; ++j) {
        CP_WAIT1();
        __syncthreads();

        if (j + 2 < NACT) {
            int st_n = st_c + 2; if (st_n >= STAGES) st_n -= STAGES;
            LOAD_CHUNK(j + 2, st_n);
        }
        CP_COMMIT();

        const uint32_t stb = sbase + (uint32_t)st_c * STAGE_BYTES;
#pragma unroll
        for (int s = 0; s < 4; ++s) {
            uint32_t afr[4][4];
            uint32_t bfr[4][2];
#pragma unroll
            for (int mf = 0; mf < 4; ++mf)
                ldm_x4(afr[mf][0], afr[mf][1], afr[mf][2], afr[mf][3],
                       stb + aoff[mf] + s * 32);
#pragma unroll
            for (int np = 0; np < 2; ++np)
                ldm_x4(bfr[2 * np][0], bfr[2 * np][1],
                       bfr[2 * np + 1][0], bfr[2 * np + 1][1],
                       stb + boff[np] + s * 32);
#pragma unroll
            for (int mf = 0; mf < 4; ++mf)
#pragma unroll
                for (int nf = 0; nf < 4; ++nf)
                    mma_f16(acc[mf][nf][0], acc[mf][nf][1], acc[mf][nf][2], acc[mf][nf][3],
                            afr[mf][0], afr[mf][1], afr[mf][2], afr[mf][3],
                            bfr[nf][0], bfr[nf][1]);
        }
        ++st_c; if (st_c >= STAGES) st_c = 0;
    }
#undef LOAD_CHUNK

    // ---- rank-1 wrap-column update (folded wrap chunk) ----
    __half* sm_ac = reinterpret_cast<__half*>(smc);          // [128] A[:,1023]
    __half* sm_wc = sm_ac + 128;                             // [128] W[:,1023]
    if (rank1) {
        __syncthreads();      // all warps done reading stage buffers
        if (tid < 128)      sm_ac[tid]       = A[(size_t)(rowA0 + tid) * DIM + 1023];
        else                sm_wc[tid - 128] = W[(size_t)(colB0 + tid - 128) * DIM + 1023];
        __syncthreads();
    }

    // ---- epilogue: (rank-1) + bias + activation ----
#pragma unroll
    for (int mf = 0; mf < 4; ++mf) {
#pragma unroll
        for (int nf = 0; nf < 4; ++nf) {
            int row0 = rowA0 + warpM * 64 + mf * 16 + qr;
            int col0 = colB0 + warpN * 32 + nf * 8 + 2 * qc;
            float v0 = acc[mf][nf][0];
            float v1 = acc[mf][nf][1];
            float v2 = acc[mf][nf][2];
            float v3 = acc[mf][nf][3];
            if (rank1) {
                float ar0 = __half2float(sm_ac[warpM * 64 + mf * 16 + qr]);
                float ar1 = __half2float(sm_ac[warpM * 64 + mf * 16 + qr + 8]);
                float w0  = __half2float(sm_wc[warpN * 32 + nf * 8 + 2 * qc]);
                float w1  = __half2float(sm_wc[warpN * 32 + nf * 8 + 2 * qc + 1]);
                v0 = fmaf(ar0, w0, v0);
                v1 = fmaf(ar0, w1, v1);
                v2 = fmaf(ar1, w0, v2);
                v3 = fmaf(ar1, w1, v3);
            }
            float b0 = bias[col0];
            float b1 = bias[col0 + 1];
            v0 += b0; v1 += b1; v2 += b0; v3 += b1;
            if (act == ACT_TANH) {
                v0 = tanhf(v0); v1 = tanhf(v1); v2 = tanhf(v2); v3 = tanhf(v3);
            } else if (act == ACT_RELU) {
                v0 = fmaxf(v0, 0.f); v1 = fmaxf(v1, 0.f);
                v2 = fmaxf(v2, 0.f); v3 = fmaxf(v3, 0.f);
            }
            if (layer < 2) {   // __half intermediate
                __half2* p0 = reinterpret_cast<__half2*>((__half*)C + (size_t)row0 * DIM + col0);
                __half2* p1 = reinterpret_cast<__half2*>((__half*)C + (size_t)(row0 + 8) * DIM + col0);
                *p0 = __floats2half2_rn(v0, v1);
                *p1 = __floats2half2_rn(v2, v3);
            } else {            // float output (m / a)
                *reinterpret_cast<float2*>((float*)C + (size_t)row0 * DIM + col0)       = make_float2(v0, v1);
                *reinterpret_cast<float2*>((float*)C + (size_t)(row0 + 8) * DIM + col0) = make_float2(v2, v3);
            }
        }
    }

    // ---- signal completion (layers 0,1 feed a consumer) ----
    if (layer < 2) {
        __threadfence();
        __syncthreads();
        if (tid == 0) atomicAdd(&g_done[layer][b][y], 1u);
    }
}

// ---------------- final elementwise + logdet (2 rows/block, MLP=2) -----------
__global__ void final_kernel(const float* __restrict__ x, const float* __restrict__ m,
                             const float* __restrict__ a, float* __restrict__ out) {
    const int t   = threadIdx.x;
    const int row = blockIdx.x * 2 + (t >> 7);   // 2 rows per block
    const int j   = t & 127;                      // float4 lane within row
    const size_t rb4 = (size_t)row * (DIM / 4);
    const float4* ar = reinterpret_cast<const float4*>(a);
    const float4* mr = reinterpret_cast<const float4*>(m);
    const float4* xr = reinterpret_cast<const float4*>(x);
    float4* ur = reinterpret_cast<float4*>(out);

    float4 a0 = ar[rb4 + j];
    float4 a1 = ar[rb4 + j + 128];
    float4 m0 = mr[rb4 + j];
    float4 m1 = mr[rb4 + j + 128];
    float4 x0 = xr[rb4 + j];
    float4 x1 = xr[rb4 + j + 128];
    float4 u0, u1;
    u0.x = (x0.x - m0.x) * expf(-a0.x);
    u0.y = (x0.y - m0.y) * expf(-a0.y);
    u0.z = (x0.z - m0.z) * expf(-a0.z);
    u0.w = (x0.w - m0.w) * expf(-a0.w);
    u1.x = (x1.x - m1.x) * expf(-a1.x);
    u1.y = (x1.y - m1.y) * expf(-a1.y);
    u1.z = (x1.z - m1.z) * expf(-a1.z);
    u1.w = (x1.w - m1.w) * expf(-a1.w);
    ur[rb4 + j]       = u0;
    ur[rb4 + j + 128] = u1;

    float s = a0.x + a0.y + a0.z + a0.w + a1.x + a1.y + a1.z + a1.w;
#pragma unroll
    for (int o = 16; o; o >>= 1) s += __shfl_down_sync(0xFFFFFFFFu, s, o);
    __shared__ float ws[8];
    if ((t & 31) == 0) ws[t >> 5] = s;
    __syncthreads();
    if ((t & 127) == 0) {
        const int wbase = (t >> 7) * 4;
        float v = ws[wbase] + ws[wbase + 1] + ws[wbase + 2] + ws[wbase + 3];
        out[(size_t)BATCH * DIM + row] = -v;
    }
}

// ---------------- launcher ---------------------------------------------------
extern "C" void kernel_launch(void* const* d_in, const int* in_sizes, int n_in,
                              void* d_out, int out_size) {
    (void)in_sizes; (void)n_in; (void)out_size;
    const float* x      = (const float*)d_in[0];
    const float* s_w1   = (const float*)d_in[1];
    const float* s_b1   = (const float*)d_in[2];
    const float* s_w2   = (const float*)d_in[3];
    const float* s_b2   = (const float*)d_in[4];
    const float* s_w3   = (const float*)d_in[5];
    const float* s_b3   = (const float*)d_in[6];
    const float* t_w1   = (const float*)d_in[7];
    const float* t_b1   = (const float*)d_in[8];
    const float* t_w2   = (const float*)d_in[9];
    const float* t_b2   = (const float*)d_in[10];
    const float* t_w3   = (const float*)d_in[11];
    const float* t_b3   = (const float*)d_in[12];
    float* out = (float*)d_out;

    __half *wm, *x16, *h1s, *h2s, *h1t, *h2t;
    float *mbuf, *abuf;
    cudaGetSymbolAddress((void**)&wm,   g_wm16);
    cudaGetSymbolAddress((void**)&x16,  g_x16);
    cudaGetSymbolAddress((void**)&h1s,  g_h1s);
    cudaGetSymbolAddress((void**)&h2s,  g_h2s);
    cudaGetSymbolAddress((void**)&h1t,  g_h1t);
    cudaGetSymbolAddress((void**)&h2t,  g_h2t);
    cudaGetSymbolAddress((void**)&mbuf, g_m);
    cudaGetSymbolAddress((void**)&abuf, g_a);

    cudaFuncSetAttribute((const void*)gemm_made_kernel,
                         cudaFuncAttributeMaxDynamicSharedMemorySize, GEMM_SMEM);

    // prepA: counter reset + x convert (MLP=2) + layer-1 weights (slots 0,3)
    prep_a<<<3072, 256>>>(s_w1, t_w1, x, wm, x16);

    // One launch: prepB (zc=0, dispatched first) + 3 layers x 2 branches.
    dim3 grid(2, BATCH / 128, 25);
    gemm_made_kernel<<<grid, 256, GEMM_SMEM>>>(
        x16, h1s, h1t, h2s, h2t, wm,
        s_w2, s_w3, t_w2, t_w3,
        s_b1, s_b2, s_b3, t_b1, t_b2, t_b3, mbuf, abuf);

    final_kernel<<<BATCH / 2, 256>>>(x, mbuf, abuf, out);
}